// round 2
// baseline (speedup 1.0000x reference)
#include <cuda_runtime.h>
#include <math.h>

// Problem dims (fixed by the dataset)
#define T_STEPS 64
#define B_DIM 2048
#define U_DIM 1024

// GEMM tiling
#define TM 128
#define TN 64
#define KB 16
#define NTILE (U_DIM / TN) // 16 u-tiles

// Persistent state in device globals (no allocation allowed).
__device__ float g_h[2][B_DIM * U_DIM];   // cell state ping-pong (2 x 8 MB)
__device__ float g_x1[B_DIM];
__device__ float g_x2[B_DIM];
__device__ float g_part[B_DIM][NTILE];    // per-row partial dots c . w_out

union F4U { float4 v; unsigned long long u[2]; float f[4]; };

__device__ __forceinline__ unsigned long long pack2(float x, float y) {
    unsigned long long r;
    asm("mov.b64 %0, {%1, %2};" : "=l"(r) : "f"(x), "f"(y));
    return r;
}
__device__ __forceinline__ void ffma2(unsigned long long &d,
                                      unsigned long long a,
                                      unsigned long long b) {
    // packed f32x2 FMA: full-rate 128 FMA/cyc/SM on sm_103a (FFMA-3reg is half rate)
    asm("fma.rn.f32x2 %0, %1, %2, %0;" : "+l"(d) : "l"(a), "l"(b));
}
__device__ __forceinline__ float2 unpack2(unsigned long long v) {
    float2 r;
    asm("mov.b64 {%0, %1}, %2;" : "=f"(r.x), "=f"(r.y) : "l"(v));
    return r;
}

__global__ void init_state(const float* __restrict__ x1_0,
                           const float* __restrict__ x2_0,
                           const float* __restrict__ c0) {
    int i = blockIdx.x * blockDim.x + threadIdx.x;
    int stride = gridDim.x * blockDim.x;
    if (i < B_DIM) { g_x1[i] = x1_0[i]; g_x2[i] = x2_0[i]; }
    for (int j = i; j < B_DIM * U_DIM; j += stride) g_h[0][j] = c0[j];
}

// One timestep: x_f/x_c = h@R(+x1*K+b), gate, new c, and per-row partial c.w_out.
// grid = (U/TN=16, B/TM=16), 256 threads.
__global__ __launch_bounds__(256, 2)
void step_gemm(const float* __restrict__ R,     // (U, 2U) row-major
               const float* __restrict__ Kmat,  // (1, 2U)
               const float* __restrict__ bias,  // (2U)
               const float* __restrict__ wout,  // (U)
               int par)
{
    __shared__ float Hs[KB][TM];     // transposed h tile
    __shared__ float Rfs[KB][TN];
    __shared__ float Rcs[KB][TN];
    __shared__ float red[TM][16];    // per-row partial reduction across tx groups

    const float* __restrict__ h  = g_h[par];
    float* __restrict__ hn = g_h[par ^ 1];

    const int b0 = blockIdx.y * TM;
    const int u0 = blockIdx.x * TN;
    const int tid = threadIdx.x;
    const int tx = tid & 15;   // u group: 4 u's each
    const int ty = tid >> 4;   // row group: 8 rows each

    unsigned long long accf[8][2];
    unsigned long long accc[8][2];
#pragma unroll
    for (int r = 0; r < 8; r++) {
        accf[r][0] = 0ull; accf[r][1] = 0ull;
        accc[r][0] = 0ull; accc[r][1] = 0ull;
    }

    const int hr = tid >> 1;          // 0..127 row for H load
    const int hk = (tid & 1) * 8;     // k offset 0 or 8
    const int rk = tid >> 4;          // 0..15 k for R load
    const int ru = (tid & 15) * 4;    // u offset

    for (int k0 = 0; k0 < U_DIM; k0 += KB) {
        // load H tile 128 rows x 16 k, store transposed
        F4U h0a, h1a;
        h0a.v = *(const float4*)&h[(b0 + hr) * U_DIM + k0 + hk];
        h1a.v = *(const float4*)&h[(b0 + hr) * U_DIM + k0 + hk + 4];
#pragma unroll
        for (int j = 0; j < 4; j++) {
            Hs[hk + j][hr]     = h0a.f[j];
            Hs[hk + 4 + j][hr] = h1a.f[j];
        }
        // load Rf / Rc tiles 16 k x 64 u
        F4U rfl, rcl;
        rfl.v = *(const float4*)&R[(k0 + rk) * (2 * U_DIM) + u0 + ru];
        rcl.v = *(const float4*)&R[(k0 + rk) * (2 * U_DIM) + U_DIM + u0 + ru];
        *(float4*)&Rfs[rk][ru] = rfl.v;
        *(float4*)&Rcs[rk][ru] = rcl.v;
        __syncthreads();

#pragma unroll
        for (int kk = 0; kk < KB; kk++) {
            F4U a0, a1, bfv, bcv;
            a0.v  = *(const float4*)&Hs[kk][ty * 8];
            a1.v  = *(const float4*)&Hs[kk][ty * 8 + 4];
            bfv.v = *(const float4*)&Rfs[kk][tx * 4];
            bcv.v = *(const float4*)&Rcs[kk][tx * 4];
            float ar[8] = {a0.f[0], a0.f[1], a0.f[2], a0.f[3],
                           a1.f[0], a1.f[1], a1.f[2], a1.f[3]};
#pragma unroll
            for (int r = 0; r < 8; r++) {
                unsigned long long aa = pack2(ar[r], ar[r]);
                ffma2(accf[r][0], aa, bfv.u[0]);
                ffma2(accf[r][1], aa, bfv.u[1]);
                ffma2(accc[r][0], aa, bcv.u[0]);
                ffma2(accc[r][1], aa, bcv.u[1]);
            }
        }
        __syncthreads();
    }

    // epilogue: add input/bias terms, gate, write new c, accumulate c.w_out
    float kf[4], kc[4], bfc[4], bcc[4], wv[4];
    const int ub = u0 + tx * 4;
#pragma unroll
    for (int j = 0; j < 4; j++) {
        kf[j]  = Kmat[ub + j];
        kc[j]  = Kmat[U_DIM + ub + j];
        bfc[j] = bias[ub + j];
        bcc[j] = bias[U_DIM + ub + j];
        wv[j]  = wout[ub + j];
    }
    float wsum[8];
#pragma unroll
    for (int r = 0; r < 8; r++) {
        const int b = b0 + ty * 8 + r;
        const float x1v = g_x1[b];
        float2 f0 = unpack2(accf[r][0]);
        float2 f1 = unpack2(accf[r][1]);
        float2 c0v = unpack2(accc[r][0]);
        float2 c1v = unpack2(accc[r][1]);
        float af[4] = {f0.x, f0.y, f1.x, f1.y};
        float ac[4] = {c0v.x, c0v.y, c1v.x, c1v.y};
        float ws = 0.f;
#pragma unroll
        for (int j = 0; j < 4; j++) {
            float xf = af[j] + x1v * kf[j] + bfc[j];
            float xc = ac[j] + x1v * kc[j] + bcc[j];
            float fg = 1.f / (1.f + expf(-xf));
            float hv = h[b * U_DIM + ub + j];
            float cv = fg * hv + (1.f - fg) * tanhf(xc);
            hn[b * U_DIM + ub + j] = cv;
            ws += cv * wv[j];
        }
        wsum[r] = ws;
    }
#pragma unroll
    for (int r = 0; r < 8; r++) red[ty * 8 + r][tx] = wsum[r];
    __syncthreads();
    if (tid < TM) {
        float s = 0.f;
#pragma unroll
        for (int j = 0; j < 16; j++) s += red[tid][j];
        g_part[b0 + tid][blockIdx.x] = s;
    }
}

// Finish the step: dot = c.w_out; x1 += x2; x2 += inp*dot; emit x1_new.
__global__ void step_update(const float* __restrict__ inp,
                            float* __restrict__ out, int t) {
    int b = blockIdx.x * blockDim.x + threadIdx.x;
    if (b >= B_DIM) return;
    float dot = 0.f;
#pragma unroll
    for (int n = 0; n < NTILE; n++) dot += g_part[b][n];
    float x1 = g_x1[b], x2 = g_x2[b];
    float x1n = x1 + x2;
    float x2n = x2 + inp[t * B_DIM + b] * dot;
    out[t * B_DIM + b] = x1n;
    g_x1[b] = x1n;
    g_x2[b] = x2n;
}

extern "C" void kernel_launch(void* const* d_in, const int* in_sizes, int n_in,
                              void* d_out, int out_size) {
    const float* inputs = (const float*)d_in[0];   // (T, B, 1)
    const float* x1_0   = (const float*)d_in[1];   // (B, 1)
    const float* x2_0   = (const float*)d_in[2];   // (B, 1)
    const float* c0     = (const float*)d_in[3];   // (B, U)
    const float* kmat   = (const float*)d_in[4];   // (1, 2U)
    const float* rker   = (const float*)d_in[5];   // (U, 2U)
    const float* bias   = (const float*)d_in[6];   // (2U)
    const float* wout   = (const float*)d_in[7];   // (U, 1)
    float* out = (float*)d_out;                    // (T, B, 1)

    (void)in_sizes; (void)n_in; (void)out_size;

    init_state<<<1024, 256>>>(x1_0, x2_0, c0);
    dim3 grid(U_DIM / TN, B_DIM / TM); // (16, 16)
    for (int t = 0; t < T_STEPS; t++) {
        step_gemm<<<grid, 256>>>(rker, kmat, bias, wout, t & 1);
        step_update<<<(B_DIM + 255) / 256, 256>>>(inputs, out, t);
    }
}

// round 4
// speedup vs baseline: 2.1035x; 2.1035x over previous
#include <cuda_runtime.h>
#include <cuda_bf16.h>
#include <cstdint>
#include <math.h>

#define T_STEPS 64
#define B_DIM 2048
#define U_DIM 1024
#define NTILE_U 16            // 1024/64 u-tiles
#define KB 32                 // k elements per chunk
#define NCHUNK (U_DIM / KB)   // 32

// ---------------- persistent state (no allocs allowed) ----------------
__device__ __align__(128) float g_h[2][B_DIM * U_DIM];              // fp32 cell state ping-pong
__device__ __align__(128) __nv_bfloat16 g_h_hi[2][B_DIM * U_DIM];
__device__ __align__(128) __nv_bfloat16 g_h_lo[2][B_DIM * U_DIM];
__device__ __align__(128) __nv_bfloat16 g_Rt_hi[2 * U_DIM * U_DIM]; // Rt[n][k] = R[k][n]
__device__ __align__(128) __nv_bfloat16 g_Rt_lo[2 * U_DIM * U_DIM];
__device__ float g_x1[B_DIM];
__device__ float g_x2[B_DIM];
__device__ float g_part[B_DIM][NTILE_U];

// ---------------- PTX helpers (all base-sm_103-safe) ----------------
__device__ __forceinline__ uint32_t smem_u32(const void* p) {
    uint32_t a;
    asm("{ .reg .u64 t; cvta.to.shared.u64 t, %1; cvt.u32.u64 %0, t; }" : "=r"(a) : "l"(p));
    return a;
}
#define CP16(s, g) \
    asm volatile("cp.async.cg.shared.global [%0], [%1], 16;" :: "r"(s), "l"(g) : "memory")
#define CP_COMMIT() asm volatile("cp.async.commit_group;" ::: "memory")
#define CP_WAIT1()  asm volatile("cp.async.wait_group 1;" ::: "memory")
#define CP_WAIT0()  asm volatile("cp.async.wait_group 0;" ::: "memory")

#define LDSM_X4(r, addr) \
    asm volatile("ldmatrix.sync.aligned.m8n8.x4.shared.b16 {%0,%1,%2,%3}, [%4];" \
        : "=r"((r)[0]), "=r"((r)[1]), "=r"((r)[2]), "=r"((r)[3]) : "r"(addr))
#define LDSM_X2(r, addr) \
    asm volatile("ldmatrix.sync.aligned.m8n8.x2.shared.b16 {%0,%1}, [%2];" \
        : "=r"((r)[0]), "=r"((r)[1]) : "r"(addr))

__device__ __forceinline__ void mma_bf16(float* d, const uint32_t* a, const uint32_t* b) {
    asm volatile("mma.sync.aligned.m16n8k16.row.col.f32.bf16.bf16.f32 "
        "{%0,%1,%2,%3}, {%4,%5,%6,%7}, {%8,%9}, {%0,%1,%2,%3};"
        : "+f"(d[0]), "+f"(d[1]), "+f"(d[2]), "+f"(d[3])
        : "r"(a[0]), "r"(a[1]), "r"(a[2]), "r"(a[3]), "r"(b[0]), "r"(b[1]));
}

// SMEM stage layout (padded row stride 80 B => 16B aligned + conflict-free ldmatrix)
#define RS 80
#define ST_A_HI 0
#define ST_A_LO 10240
#define ST_BF_HI 20480
#define ST_BF_LO 25600
#define ST_BC_HI 30720
#define ST_BC_LO 35840
#define STAGE 40960
#define SMEM_REQ (1024 + 2 * STAGE)

// ---------------- init kernels ----------------
__global__ void init_state(const float* __restrict__ x1_0,
                           const float* __restrict__ x2_0,
                           const float* __restrict__ c0) {
    int i = blockIdx.x * blockDim.x + threadIdx.x;
    int stride = gridDim.x * blockDim.x;
    if (i < B_DIM) { g_x1[i] = x1_0[i]; g_x2[i] = x2_0[i]; }
    for (int j = i; j < B_DIM * U_DIM; j += stride) {
        float v = c0[j];
        g_h[0][j] = v;
        __nv_bfloat16 hi = __float2bfloat16(v);
        g_h_hi[0][j] = hi;
        g_h_lo[0][j] = __float2bfloat16(v - __bfloat162float(hi));
    }
}

// Transpose R (U x 2U, row-major) -> Rt (2U x U), split into bf16 hi/lo.
__global__ void transpose_R(const float* __restrict__ R) {
    __shared__ float tile[32][33];
    const int nb = blockIdx.x * 32;   // n tile (0..2047)
    const int kb = blockIdx.y * 32;   // k tile (0..1023)
    const int tx = threadIdx.x, ty = threadIdx.y;
    for (int kk = ty; kk < 32; kk += 8)
        tile[kk][tx] = R[(kb + kk) * (2 * U_DIM) + nb + tx];
    __syncthreads();
    for (int nn = ty; nn < 32; nn += 8) {
        float v = tile[tx][nn];
        __nv_bfloat16 hi = __float2bfloat16(v);
        size_t o = (size_t)(nb + nn) * U_DIM + kb + tx;
        g_Rt_hi[o] = hi;
        g_Rt_lo[o] = __float2bfloat16(v - __bfloat162float(hi));
    }
}

// ---------------- main step kernel ----------------
// grid (16 u-tiles, 16 b-tiles), 256 threads, occ 2 => single wave of 256 CTAs.
__global__ __launch_bounds__(256, 2)
void step_gemm(const float* __restrict__ Kmat,   // (2U)
               const float* __restrict__ bias,   // (2U)
               const float* __restrict__ wout,   // (U)
               int par)
{
    extern __shared__ char smem[];
    float* red = (float*)smem;                 // [128][2]
    const uint32_t sb = smem_u32(smem);
    const uint32_t tiles = sb + 1024;

    const int tid  = threadIdx.x;
    const int lane = tid & 31;
    const int wid  = tid >> 5;
    const int mwarp = wid >> 1;                // 0..3 (32 rows each)
    const int nwarp = wid & 1;                 // 0..1 (32 cols each)
    const int b0 = blockIdx.y * 128;
    const int u0 = blockIdx.x * 64;

    const __nv_bfloat16* __restrict__ pAh = g_h_hi[par] + (size_t)b0 * U_DIM;
    const __nv_bfloat16* __restrict__ pAl = g_h_lo[par] + (size_t)b0 * U_DIM;
    const __nv_bfloat16* __restrict__ pFh = g_Rt_hi + (size_t)u0 * U_DIM;
    const __nv_bfloat16* __restrict__ pFl = g_Rt_lo + (size_t)u0 * U_DIM;
    const __nv_bfloat16* __restrict__ pCh = g_Rt_hi + (size_t)(U_DIM + u0) * U_DIM;
    const __nv_bfloat16* __restrict__ pCl = g_Rt_lo + (size_t)(U_DIM + u0) * U_DIM;

    // cp.async per-thread addressing
    const int ar0 = tid >> 2, ac0 = (tid & 3);           // A granule set 0 (rows 0..63)
    const int ar1 = 64 + (tid >> 2);                     // A granule set 1 (rows 64..127)
    const int br  = tid >> 2, bc = (tid & 3);            // B granule (rows 0..63)

#define LOADC(k0, stg) do { \
        const uint32_t s = tiles + (stg) * STAGE; \
        CP16(s + ST_A_HI + (uint32_t)(ar0 * RS + ac0 * 16), (const char*)(pAh + (size_t)ar0 * U_DIM + (k0) + ac0 * 8)); \
        CP16(s + ST_A_HI + (uint32_t)(ar1 * RS + ac0 * 16), (const char*)(pAh + (size_t)ar1 * U_DIM + (k0) + ac0 * 8)); \
        CP16(s + ST_A_LO + (uint32_t)(ar0 * RS + ac0 * 16), (const char*)(pAl + (size_t)ar0 * U_DIM + (k0) + ac0 * 8)); \
        CP16(s + ST_A_LO + (uint32_t)(ar1 * RS + ac0 * 16), (const char*)(pAl + (size_t)ar1 * U_DIM + (k0) + ac0 * 8)); \
        CP16(s + ST_BF_HI + (uint32_t)(br * RS + bc * 16), (const char*)(pFh + (size_t)br * U_DIM + (k0) + bc * 8)); \
        CP16(s + ST_BF_LO + (uint32_t)(br * RS + bc * 16), (const char*)(pFl + (size_t)br * U_DIM + (k0) + bc * 8)); \
        CP16(s + ST_BC_HI + (uint32_t)(br * RS + bc * 16), (const char*)(pCh + (size_t)br * U_DIM + (k0) + bc * 8)); \
        CP16(s + ST_BC_LO + (uint32_t)(br * RS + bc * 16), (const char*)(pCl + (size_t)br * U_DIM + (k0) + bc * 8)); \
        CP_COMMIT(); \
    } while (0)

    // ldmatrix per-lane offsets
    const uint32_t aOff = (uint32_t)((mwarp * 32 + (lane & 15)) * RS + ((lane >> 4) << 4));
    const uint32_t bOff = (uint32_t)((nwarp * 32 + (lane & 7)) * RS + (((lane >> 3) & 1) << 4));

    float acc[2][2][4][4];   // [gate][mt][nt][e]
#pragma unroll
    for (int g = 0; g < 2; g++)
#pragma unroll
        for (int mt = 0; mt < 2; mt++)
#pragma unroll
            for (int nt = 0; nt < 4; nt++)
#pragma unroll
                for (int e = 0; e < 4; e++) acc[g][mt][nt][e] = 0.f;

    LOADC(0, 0);

    for (int i = 0; i < NCHUNK; i++) {
        const int cur = i & 1;
        if (i + 1 < NCHUNK) { LOADC((i + 1) * KB, cur ^ 1); CP_WAIT1(); }
        else                { CP_WAIT0(); }
        __syncthreads();

        const uint32_t base = tiles + cur * STAGE;
        const uint32_t aHiB = base + ST_A_HI + aOff;
        const uint32_t aLoB = base + ST_A_LO + aOff;
        const uint32_t bHiB[2] = { base + ST_BF_HI + bOff, base + ST_BC_HI + bOff };
        const uint32_t bLoB[2] = { base + ST_BF_LO + bOff, base + ST_BC_LO + bOff };

#pragma unroll
        for (int kk = 0; kk < 2; kk++) {
            const uint32_t kb = kk * 32;  // 16 bf16 = 32 bytes
            uint32_t ah[2][4], al[2][4];
            LDSM_X4(ah[0], aHiB + kb);
            LDSM_X4(ah[1], aHiB + 16 * RS + kb);
            LDSM_X4(al[0], aLoB + kb);
            LDSM_X4(al[1], aLoB + 16 * RS + kb);
#pragma unroll
            for (int g = 0; g < 2; g++) {
                uint32_t bh[4][2], bl[4][2];
#pragma unroll
                for (int nt = 0; nt < 4; nt++) {
                    LDSM_X2(bh[nt], bHiB[g] + nt * 8 * RS + kb);
                    LDSM_X2(bl[nt], bLoB[g] + nt * 8 * RS + kb);
                }
#pragma unroll
                for (int mt = 0; mt < 2; mt++)
#pragma unroll
                    for (int nt = 0; nt < 4; nt++) {
                        mma_bf16(acc[g][mt][nt], ah[mt], bh[nt]);
                        mma_bf16(acc[g][mt][nt], al[mt], bh[nt]);
                        mma_bf16(acc[g][mt][nt], ah[mt], bl[nt]);
                    }
            }
        }
        __syncthreads();
    }

    // -------- epilogue (in-register: this thread owns f and c for same elems) --------
    float ws[4] = {0.f, 0.f, 0.f, 0.f};
#pragma unroll
    for (int mt = 0; mt < 2; mt++) {
#pragma unroll
        for (int e2 = 0; e2 < 2; e2++) {
            const int rl = mwarp * 32 + mt * 16 + (lane >> 2) + e2 * 8;  // local row
            const int b = b0 + rl;
            const float x1v = g_x1[b];
            const float* __restrict__ hrow = g_h[par]     + (size_t)b * U_DIM + u0;
            float* __restrict__       hnrw = g_h[par ^ 1] + (size_t)b * U_DIM + u0;
            __nv_bfloat16* __restrict__ hhi = g_h_hi[par ^ 1] + (size_t)b * U_DIM + u0;
            __nv_bfloat16* __restrict__ hlo = g_h_lo[par ^ 1] + (size_t)b * U_DIM + u0;
#pragma unroll
            for (int nt = 0; nt < 4; nt++) {
#pragma unroll
                for (int j = 0; j < 2; j++) {
                    const int e = e2 * 2 + j;
                    const int ul = nwarp * 32 + nt * 8 + (lane & 3) * 2 + j;  // local u (0..63)
                    const int ug = u0 + ul;
                    float xf = acc[0][mt][nt][e] + x1v * Kmat[ug] + bias[ug];
                    float xc = acc[1][mt][nt][e] + x1v * Kmat[U_DIM + ug] + bias[U_DIM + ug];
                    float fg = 1.f / (1.f + expf(-xf));
                    float ho = hrow[ul];
                    float cv = fg * ho + (1.f - fg) * tanhf(xc);
                    hnrw[ul] = cv;
                    __nv_bfloat16 hi = __float2bfloat16(cv);
                    hhi[ul] = hi;
                    hlo[ul] = __float2bfloat16(cv - __bfloat162float(hi));
                    ws[mt * 2 + e2] += cv * wout[ug];
                }
            }
        }
    }
    // reduce ws over the 4 lanes sharing each row, then across the 2 n-warps
#pragma unroll
    for (int w = 0; w < 4; w++) {
        float v = ws[w];
        v += __shfl_xor_sync(0xFFFFFFFFu, v, 1);
        v += __shfl_xor_sync(0xFFFFFFFFu, v, 2);
        if ((lane & 3) == 0) {
            const int rl = mwarp * 32 + (w >> 1) * 16 + (lane >> 2) + (w & 1) * 8;
            red[rl * 2 + nwarp] = v;
        }
    }
    __syncthreads();
    if (tid < 128)
        g_part[b0 + tid][blockIdx.x] = red[tid * 2] + red[tid * 2 + 1];
}

// ---------------- per-step scalar update ----------------
__global__ void step_update(const float* __restrict__ inp,
                            float* __restrict__ out, int t) {
    int b = blockIdx.x * blockDim.x + threadIdx.x;
    if (b >= B_DIM) return;
    float dot = 0.f;
#pragma unroll
    for (int n = 0; n < NTILE_U; n++) dot += g_part[b][n];
    float x1 = g_x1[b], x2 = g_x2[b];
    float x1n = x1 + x2;
    float x2n = x2 + inp[t * B_DIM + b] * dot;
    out[t * B_DIM + b] = x1n;
    g_x1[b] = x1n;
    g_x2[b] = x2n;
}

extern "C" void kernel_launch(void* const* d_in, const int* in_sizes, int n_in,
                              void* d_out, int out_size) {
    const float* inputs = (const float*)d_in[0];   // (T, B, 1)
    const float* x1_0   = (const float*)d_in[1];   // (B, 1)
    const float* x2_0   = (const float*)d_in[2];   // (B, 1)
    const float* c0     = (const float*)d_in[3];   // (B, U)
    const float* kmat   = (const float*)d_in[4];   // (1, 2U)
    const float* rker   = (const float*)d_in[5];   // (U, 2U)
    const float* bias   = (const float*)d_in[6];   // (2U)
    const float* wout   = (const float*)d_in[7];   // (U, 1)
    float* out = (float*)d_out;                    // (T, B, 1)
    (void)in_sizes; (void)n_in; (void)out_size;

    cudaFuncSetAttribute(step_gemm, cudaFuncAttributeMaxDynamicSharedMemorySize, SMEM_REQ);

    init_state<<<1024, 256>>>(x1_0, x2_0, c0);
    transpose_R<<<dim3(2 * U_DIM / 32, U_DIM / 32), dim3(32, 8)>>>(rker);

    dim3 grid(NTILE_U, B_DIM / 128);  // (16, 16)
    for (int t = 0; t < T_STEPS; t++) {
        step_gemm<<<grid, 256, SMEM_REQ>>>(kmat, bias, wout, t & 1);
        step_update<<<(B_DIM + 255) / 256, 256>>>(inputs, out, t);
    }
}

// round 8
// speedup vs baseline: 2.1327x; 1.0139x over previous
#include <cuda_runtime.h>
#include <cuda_bf16.h>
#include <cstdint>
#include <math.h>

#define T_STEPS 64
#define B_DIM 2048
#define U_DIM 1024
#define NTILE_U 16            // 1024/64 u-tiles
#define NTILE_B 16            // 2048/128 b-tiles
#define KB 32                 // k elements per chunk
#define NCHUNK (U_DIM / KB)   // 32

// ---------------- persistent state (no allocs allowed) ----------------
__device__ __align__(128) __nv_bfloat16 g_h_hi[2][B_DIM * U_DIM];
__device__ __align__(128) __nv_bfloat16 g_h_lo[2][B_DIM * U_DIM];
__device__ __align__(128) __nv_bfloat16 g_Rt_hi[2 * U_DIM * U_DIM]; // Rt[n][k] = R[k][n]
__device__ __align__(128) __nv_bfloat16 g_Rt_lo[2 * U_DIM * U_DIM];
__device__ float g_x1[2][B_DIM];
__device__ float g_x2[2][B_DIM];
__device__ float g_part[B_DIM][NTILE_U];
__device__ int   g_tick[T_STEPS][NTILE_B];

// ---------------- PTX helpers (base-sm_103-safe) ----------------
__device__ __forceinline__ uint32_t smem_u32(const void* p) {
    uint32_t a;
    asm("{ .reg .u64 t; cvta.to.shared.u64 t, %1; cvt.u32.u64 %0, t; }" : "=r"(a) : "l"(p));
    return a;
}
#define CP16(s, g) \
    asm volatile("cp.async.cg.shared.global [%0], [%1], 16;" :: "r"(s), "l"(g) : "memory")
#define CP_COMMIT() asm volatile("cp.async.commit_group;" ::: "memory")
#define CP_WAIT1()  asm volatile("cp.async.wait_group 1;" ::: "memory")
#define CP_WAIT0()  asm volatile("cp.async.wait_group 0;" ::: "memory")

#define LDSM_X4(r, addr) \
    asm volatile("ldmatrix.sync.aligned.m8n8.x4.shared.b16 {%0,%1,%2,%3}, [%4];" \
        : "=r"((r)[0]), "=r"((r)[1]), "=r"((r)[2]), "=r"((r)[3]) : "r"(addr))

__device__ __forceinline__ void mma_bf16(float* d, const uint32_t* a, const uint32_t* b) {
    asm volatile("mma.sync.aligned.m16n8k16.row.col.f32.bf16.bf16.f32 "
        "{%0,%1,%2,%3}, {%4,%5,%6,%7}, {%8,%9}, {%0,%1,%2,%3};"
        : "+f"(d[0]), "+f"(d[1]), "+f"(d[2]), "+f"(d[3])
        : "r"(a[0]), "r"(a[1]), "r"(a[2]), "r"(a[3]), "r"(b[0]), "r"(b[1]));
}

// SMEM stage layout (padded row stride 80 B => 16B aligned + conflict-free ldmatrix)
#define RS 80
#define ST_A_HI 0
#define ST_A_LO 10240
#define ST_BF_HI 20480
#define ST_BF_LO 25600
#define ST_BC_HI 30720
#define ST_BC_LO 35840
#define STAGE 40960
#define SMEM_REQ (1024 + 2 * STAGE)

// ---------------- init kernels ----------------
__global__ void init_state(const float* __restrict__ x1_0,
                           const float* __restrict__ x2_0,
                           const float* __restrict__ c0) {
    int i = blockIdx.x * blockDim.x + threadIdx.x;
    int stride = gridDim.x * blockDim.x;
    if (i < B_DIM) { g_x1[0][i] = x1_0[i]; g_x2[0][i] = x2_0[i]; }
    if (i < T_STEPS * NTILE_B) ((int*)g_tick)[i] = 0;
    for (int j = i; j < B_DIM * U_DIM; j += stride) {
        float v = c0[j];
        __nv_bfloat16 hi = __float2bfloat16(v);
        g_h_hi[0][j] = hi;
        g_h_lo[0][j] = __float2bfloat16(v - __bfloat162float(hi));
    }
}

// Transpose R (U x 2U, row-major) -> Rt (2U x U), split into bf16 hi/lo.
__global__ void transpose_R(const float* __restrict__ R) {
    __shared__ float tile[32][33];
    const int nb = blockIdx.x * 32;   // n tile (0..2047)
    const int kb = blockIdx.y * 32;   // k tile (0..1023)
    const int tx = threadIdx.x, ty = threadIdx.y;
    for (int kk = ty; kk < 32; kk += 8)
        tile[kk][tx] = R[(kb + kk) * (2 * U_DIM) + nb + tx];
    __syncthreads();
    for (int nn = ty; nn < 32; nn += 8) {
        float v = tile[tx][nn];
        __nv_bfloat16 hi = __float2bfloat16(v);
        size_t o = (size_t)(nb + nn) * U_DIM + kb + tx;
        g_Rt_hi[o] = hi;
        g_Rt_lo[o] = __float2bfloat16(v - __bfloat162float(hi));
    }
}

// ---------------- main step kernel ----------------
// grid (16 u-tiles, 16 b-tiles), 256 threads, occ 2 => single wave of 256 CTAs.
__global__ __launch_bounds__(256, 2)
void step_gemm(const float* __restrict__ Kmat,   // (2U)
               const float* __restrict__ bias,   // (2U)
               const float* __restrict__ wout,   // (U)
               const float* __restrict__ inp,    // (T, B)
               float* __restrict__ out,          // (T, B)
               int t)
{
    extern __shared__ char smem[];
    float* red = (float*)smem;                 // [128][2]
    int* sflag = (int*)(smem + 512);
    const uint32_t sb = smem_u32(smem);
    const uint32_t tiles = sb + 1024;
    const int par = t & 1;

    const int tid  = threadIdx.x;
    const int lane = tid & 31;
    const int wid  = tid >> 5;
    const int mwarp = wid >> 1;                // 0..3 (32 rows each)
    const int nwarp = wid & 1;                 // 0..1 (32 cols each)
    const int b0 = blockIdx.y * 128;
    const int u0 = blockIdx.x * 64;

    const __nv_bfloat16* __restrict__ pAh = g_h_hi[par] + (size_t)b0 * U_DIM;
    const __nv_bfloat16* __restrict__ pAl = g_h_lo[par] + (size_t)b0 * U_DIM;
    const __nv_bfloat16* __restrict__ pFh = g_Rt_hi + (size_t)u0 * U_DIM;
    const __nv_bfloat16* __restrict__ pFl = g_Rt_lo + (size_t)u0 * U_DIM;
    const __nv_bfloat16* __restrict__ pCh = g_Rt_hi + (size_t)(U_DIM + u0) * U_DIM;
    const __nv_bfloat16* __restrict__ pCl = g_Rt_lo + (size_t)(U_DIM + u0) * U_DIM;

    // cp.async per-thread addressing
    const int ar0 = tid >> 2, ac0 = (tid & 3);           // A granule set 0 (rows 0..63)
    const int ar1 = 64 + (tid >> 2);                     // A granule set 1 (rows 64..127)
    const int br  = tid >> 2, bc = (tid & 3);            // B granule (rows 0..63)

#define LOADC(k0, stg) do { \
        const uint32_t s = tiles + (stg) * STAGE; \
        CP16(s + ST_A_HI + (uint32_t)(ar0 * RS + ac0 * 16), (const char*)(pAh + (size_t)ar0 * U_DIM + (k0) + ac0 * 8)); \
        CP16(s + ST_A_HI + (uint32_t)(ar1 * RS + ac0 * 16), (const char*)(pAh + (size_t)ar1 * U_DIM + (k0) + ac0 * 8)); \
        CP16(s + ST_A_LO + (uint32_t)(ar0 * RS + ac0 * 16), (const char*)(pAl + (size_t)ar0 * U_DIM + (k0) + ac0 * 8)); \
        CP16(s + ST_A_LO + (uint32_t)(ar1 * RS + ac0 * 16), (const char*)(pAl + (size_t)ar1 * U_DIM + (k0) + ac0 * 8)); \
        CP16(s + ST_BF_HI + (uint32_t)(br * RS + bc * 16), (const char*)(pFh + (size_t)br * U_DIM + (k0) + bc * 8)); \
        CP16(s + ST_BF_LO + (uint32_t)(br * RS + bc * 16), (const char*)(pFl + (size_t)br * U_DIM + (k0) + bc * 8)); \
        CP16(s + ST_BC_HI + (uint32_t)(br * RS + bc * 16), (const char*)(pCh + (size_t)br * U_DIM + (k0) + bc * 8)); \
        CP16(s + ST_BC_LO + (uint32_t)(br * RS + bc * 16), (const char*)(pCl + (size_t)br * U_DIM + (k0) + bc * 8)); \
        CP_COMMIT(); \
    } while (0)

    // ldmatrix per-lane offsets
    const uint32_t aOff = (uint32_t)((mwarp * 32 + (lane & 15)) * RS + ((lane >> 4) << 4));
    // X4 B offset covering two adjacent n8 tiles: lanes 0-15 -> nt even, 16-31 -> nt odd
    const uint32_t bOff4 = (uint32_t)((nwarp * 32 + ((lane >> 4) << 3) + (lane & 7)) * RS +
                                      (((lane >> 3) & 1) << 4));

    float acc[2][2][4][4];   // [gate][mt][nt][e]
#pragma unroll
    for (int g = 0; g < 2; g++)
#pragma unroll
        for (int mt = 0; mt < 2; mt++)
#pragma unroll
            for (int nt = 0; nt < 4; nt++)
#pragma unroll
                for (int e = 0; e < 4; e++) acc[g][mt][nt][e] = 0.f;

    LOADC(0, 0);

    for (int i = 0; i < NCHUNK; i++) {
        const int cur = i & 1;
        if (i + 1 < NCHUNK) { LOADC((i + 1) * KB, cur ^ 1); CP_WAIT1(); }
        else                { CP_WAIT0(); }
        __syncthreads();

        const uint32_t base = tiles + cur * STAGE;
        const uint32_t aHiB = base + ST_A_HI + aOff;
        const uint32_t aLoB = base + ST_A_LO + aOff;
        const uint32_t bHiB[2] = { base + ST_BF_HI + bOff4, base + ST_BC_HI + bOff4 };
        const uint32_t bLoB[2] = { base + ST_BF_LO + bOff4, base + ST_BC_LO + bOff4 };

#pragma unroll
        for (int kk = 0; kk < 2; kk++) {
            const uint32_t kb = kk * 32;  // 16 bf16 = 32 bytes
            uint32_t ah[2][4], al[2][4];
            LDSM_X4(ah[0], aHiB + kb);
            LDSM_X4(ah[1], aHiB + 16 * RS + kb);
            LDSM_X4(al[0], aLoB + kb);
            LDSM_X4(al[1], aLoB + 16 * RS + kb);
#pragma unroll
            for (int g = 0; g < 2; g++) {
                uint32_t bh[2][4], bl[2][4];   // [pair][4 regs: nt_even(2), nt_odd(2)]
#pragma unroll
                for (int p = 0; p < 2; p++) {
                    LDSM_X4(bh[p], bHiB[g] + p * 16 * RS + kb);
                    LDSM_X4(bl[p], bLoB[g] + p * 16 * RS + kb);
                }
#pragma unroll
                for (int mt = 0; mt < 2; mt++)
#pragma unroll
                    for (int nt = 0; nt < 4; nt++) {
                        const uint32_t* bhf = &bh[nt >> 1][(nt & 1) * 2];
                        const uint32_t* blf = &bl[nt >> 1][(nt & 1) * 2];
                        mma_bf16(acc[g][mt][nt], ah[mt], bhf);
                        mma_bf16(acc[g][mt][nt], al[mt], bhf);
                        mma_bf16(acc[g][mt][nt], ah[mt], blf);
                    }
            }
        }
        __syncthreads();
    }

    // -------- epilogue (in-register: this thread owns f and c for same elems) --------
    float ws[4] = {0.f, 0.f, 0.f, 0.f};
#pragma unroll
    for (int mt = 0; mt < 2; mt++) {
#pragma unroll
        for (int e2 = 0; e2 < 2; e2++) {
            const int rl = mwarp * 32 + mt * 16 + (lane >> 2) + e2 * 8;  // local row
            const int b = b0 + rl;
            const float x1v = g_x1[par][b];
            const __nv_bfloat16* __restrict__ ohi = g_h_hi[par] + (size_t)b * U_DIM + u0;
            const __nv_bfloat16* __restrict__ olo = g_h_lo[par] + (size_t)b * U_DIM + u0;
            __nv_bfloat16* __restrict__ hhi = g_h_hi[par ^ 1] + (size_t)b * U_DIM + u0;
            __nv_bfloat16* __restrict__ hlo = g_h_lo[par ^ 1] + (size_t)b * U_DIM + u0;
#pragma unroll
            for (int nt = 0; nt < 4; nt++) {
#pragma unroll
                for (int j = 0; j < 2; j++) {
                    const int e = e2 * 2 + j;
                    const int ul = nwarp * 32 + nt * 8 + (lane & 3) * 2 + j;  // local u (0..63)
                    const int ug = u0 + ul;
                    float xf = acc[0][mt][nt][e] + x1v * Kmat[ug] + bias[ug];
                    float xc = acc[1][mt][nt][e] + x1v * Kmat[U_DIM + ug] + bias[U_DIM + ug];
                    // sigmoid / tanh via fast ex2 + rcp (saturate correctly at +/-inf)
                    float fg = __fdividef(1.f, 1.f + __expf(-xf));
                    float th = 1.f - __fdividef(2.f, __expf(2.f * xc) + 1.f);
                    float ho = __bfloat162float(ohi[ul]) + __bfloat162float(olo[ul]);
                    float cv = fg * ho + (1.f - fg) * th;
                    __nv_bfloat16 hi = __float2bfloat16(cv);
                    hhi[ul] = hi;
                    hlo[ul] = __float2bfloat16(cv - __bfloat162float(hi));
                    ws[mt * 2 + e2] += cv * wout[ug];
                }
            }
        }
    }
    // reduce ws over the 4 lanes sharing each row, then across the 2 n-warps
#pragma unroll
    for (int w = 0; w < 4; w++) {
        float v = ws[w];
        v += __shfl_xor_sync(0xFFFFFFFFu, v, 1);
        v += __shfl_xor_sync(0xFFFFFFFFu, v, 2);
        if ((lane & 3) == 0) {
            const int rl = mwarp * 32 + (w >> 1) * 16 + (lane >> 2) + (w & 1) * 8;
            red[rl * 2 + nwarp] = v;
        }
    }
    __syncthreads();
    if (tid < 128)
        g_part[b0 + tid][blockIdx.x] = red[tid * 2] + red[tid * 2 + 1];

    // -------- last-CTA-per-b-row finisher: x1/x2/out update --------
    __threadfence();
    __syncthreads();
    if (tid == 0)
        sflag[0] = atomicAdd(&g_tick[t][blockIdx.y], 1);
    __syncthreads();
    if (sflag[0] == NTILE_U - 1) {
        __threadfence();   // acquire: make other CTAs' g_part writes visible
        if (tid < 128) {
            const int b = b0 + tid;
            float dot = 0.f;
#pragma unroll
            for (int n = 0; n < NTILE_U; n++) dot += g_part[b][n];
            float x1 = g_x1[par][b], x2 = g_x2[par][b];
            float x1n = x1 + x2;
            float x2n = x2 + inp[t * B_DIM + b] * dot;
            out[t * B_DIM + b] = x1n;
            g_x1[par ^ 1][b] = x1n;
            g_x2[par ^ 1][b] = x2n;
        }
    }
}

extern "C" void kernel_launch(void* const* d_in, const int* in_sizes, int n_in,
                              void* d_out, int out_size) {
    const float* inputs = (const float*)d_in[0];   // (T, B, 1)
    const float* x1_0   = (const float*)d_in[1];   // (B, 1)
    const float* x2_0   = (const float*)d_in[2];   // (B, 1)
    const float* c0     = (const float*)d_in[3];   // (B, U)
    const float* kmat   = (const float*)d_in[4];   // (1, 2U)
    const float* rker   = (const float*)d_in[5];   // (U, 2U)
    const float* bias   = (const float*)d_in[6];   // (2U)
    const float* wout   = (const float*)d_in[7];   // (U, 1)
    float* out = (float*)d_out;                    // (T, B, 1)
    (void)in_sizes; (void)n_in; (void)out_size;

    cudaFuncSetAttribute(step_gemm, cudaFuncAttributeMaxDynamicSharedMemorySize, SMEM_REQ);

    init_state<<<1024, 256>>>(x1_0, x2_0, c0);
    transpose_R<<<dim3(2 * U_DIM / 32, U_DIM / 32), dim3(32, 8)>>>(rker);

    dim3 grid(NTILE_U, NTILE_B);  // (16, 16)
    for (int t = 0; t < T_STEPS; t++)
        step_gemm<<<grid, 256, SMEM_REQ>>>(kmat, bias, wout, inputs, out, t);
}

// round 9
// speedup vs baseline: 2.1957x; 1.0296x over previous
#include <cuda_runtime.h>
#include <cuda_bf16.h>
#include <cstdint>
#include <math.h>

#define T_STEPS 64
#define B_DIM 2048
#define U_DIM 1024
#define NTILE_U 8             // 1024/128 u-tiles
#define NTILE_B 16            // 2048/128 b-tiles
#define KB 32                 // k elements per chunk
#define NCHUNK (U_DIM / KB)   // 32

// ---------------- persistent state (no allocs allowed) ----------------
__device__ __align__(128) __nv_bfloat16 g_h_hi[2][B_DIM * U_DIM];
__device__ __align__(128) __nv_bfloat16 g_h_lo[2][B_DIM * U_DIM];
__device__ __align__(128) __nv_bfloat16 g_Rt_hi[2 * U_DIM * U_DIM]; // Rt[n][k] = R[k][n]
__device__ __align__(128) __nv_bfloat16 g_Rt_lo[2 * U_DIM * U_DIM];
__device__ float g_x1[2][B_DIM];
__device__ float g_x2[2][B_DIM];
__device__ float g_part[B_DIM][NTILE_U];
__device__ int   g_tick[T_STEPS][NTILE_B];

// ---------------- PTX helpers (base-sm_103-safe) ----------------
__device__ __forceinline__ uint32_t smem_u32(const void* p) {
    uint32_t a;
    asm("{ .reg .u64 t; cvta.to.shared.u64 t, %1; cvt.u32.u64 %0, t; }" : "=r"(a) : "l"(p));
    return a;
}
#define CP16(s, g) \
    asm volatile("cp.async.cg.shared.global [%0], [%1], 16;" :: "r"(s), "l"(g) : "memory")
#define CP_COMMIT() asm volatile("cp.async.commit_group;" ::: "memory")
#define CP_WAIT1()  asm volatile("cp.async.wait_group 1;" ::: "memory")
#define CP_WAIT0()  asm volatile("cp.async.wait_group 0;" ::: "memory")

#define LDSM_X4(r, addr) \
    asm volatile("ldmatrix.sync.aligned.m8n8.x4.shared.b16 {%0,%1,%2,%3}, [%4];" \
        : "=r"((r)[0]), "=r"((r)[1]), "=r"((r)[2]), "=r"((r)[3]) : "r"(addr))

__device__ __forceinline__ void mma_bf16(float* d, const uint32_t* a, const uint32_t* b) {
    asm volatile("mma.sync.aligned.m16n8k16.row.col.f32.bf16.bf16.f32 "
        "{%0,%1,%2,%3}, {%4,%5,%6,%7}, {%8,%9}, {%0,%1,%2,%3};"
        : "+f"(d[0]), "+f"(d[1]), "+f"(d[2]), "+f"(d[3])
        : "r"(a[0]), "r"(a[1]), "r"(a[2]), "r"(a[3]), "r"(b[0]), "r"(b[1]));
}

// SMEM stage layout: 6 tiles of 128 rows x 32 k bf16, padded row stride 80 B
#define RS 80
#define TILE_B (128 * RS)       // 10240
#define ST_A_HI 0
#define ST_A_LO (1 * TILE_B)
#define ST_BF_HI (2 * TILE_B)
#define ST_BF_LO (3 * TILE_B)
#define ST_BC_HI (4 * TILE_B)
#define ST_BC_LO (5 * TILE_B)
#define STAGE (6 * TILE_B)      // 61440
#define NSTAGE 3
#define SMEM_HDR 3072           // red[128][4] floats (2048) + sflag + pad
#define SMEM_REQ (SMEM_HDR + NSTAGE * STAGE)

// ---------------- init kernels ----------------
__global__ void init_state(const float* __restrict__ x1_0,
                           const float* __restrict__ x2_0,
                           const float* __restrict__ c0) {
    int i = blockIdx.x * blockDim.x + threadIdx.x;
    int stride = gridDim.x * blockDim.x;
    if (i < B_DIM) { g_x1[0][i] = x1_0[i]; g_x2[0][i] = x2_0[i]; }
    if (i < T_STEPS * NTILE_B) ((int*)g_tick)[i] = 0;
    for (int j = i; j < B_DIM * U_DIM; j += stride) {
        float v = c0[j];
        __nv_bfloat16 hi = __float2bfloat16(v);
        g_h_hi[0][j] = hi;
        g_h_lo[0][j] = __float2bfloat16(v - __bfloat162float(hi));
    }
}

// Transpose R (U x 2U, row-major) -> Rt (2U x U), split into bf16 hi/lo.
__global__ void transpose_R(const float* __restrict__ R) {
    __shared__ float tile[32][33];
    const int nb = blockIdx.x * 32;   // n tile (0..2047)
    const int kb = blockIdx.y * 32;   // k tile (0..1023)
    const int tx = threadIdx.x, ty = threadIdx.y;
    for (int kk = ty; kk < 32; kk += 8)
        tile[kk][tx] = R[(kb + kk) * (2 * U_DIM) + nb + tx];
    __syncthreads();
    for (int nn = ty; nn < 32; nn += 8) {
        float v = tile[tx][nn];
        __nv_bfloat16 hi = __float2bfloat16(v);
        size_t o = (size_t)(nb + nn) * U_DIM + kb + tx;
        g_Rt_hi[o] = hi;
        g_Rt_lo[o] = __float2bfloat16(v - __bfloat162float(hi));
    }
}

// ---------------- main step kernel ----------------
// grid (8 u-tiles, 16 b-tiles) = 128 CTAs, 512 threads, occ 1 => one CTA per SM.
__global__ __launch_bounds__(512, 1)
void step_gemm(const float* __restrict__ Kmat,   // (2U)
               const float* __restrict__ bias,   // (2U)
               const float* __restrict__ wout,   // (U)
               const float* __restrict__ inp,    // (T, B)
               float* __restrict__ out,          // (T, B)
               int t)
{
    extern __shared__ char smem[];
    float* red = (float*)smem;                 // [128][4]
    int* sflag = (int*)(smem + 2048);
    const uint32_t sb = smem_u32(smem);
    const uint32_t tiles = sb + SMEM_HDR;
    const int par = t & 1;

    const int tid  = threadIdx.x;
    const int lane = tid & 31;
    const int wid  = tid >> 5;                 // 0..15
    const int mwarp = wid & 3;                 // 4 x 32 rows
    const int nwarp = wid >> 2;                // 4 x 32 cols
    const int b0 = blockIdx.y * 128;
    const int u0 = blockIdx.x * 128;

    const __nv_bfloat16* __restrict__ pAh = g_h_hi[par] + (size_t)b0 * U_DIM;
    const __nv_bfloat16* __restrict__ pAl = g_h_lo[par] + (size_t)b0 * U_DIM;
    const __nv_bfloat16* __restrict__ pFh = g_Rt_hi + (size_t)u0 * U_DIM;
    const __nv_bfloat16* __restrict__ pFl = g_Rt_lo + (size_t)u0 * U_DIM;
    const __nv_bfloat16* __restrict__ pCh = g_Rt_hi + (size_t)(U_DIM + u0) * U_DIM;
    const __nv_bfloat16* __restrict__ pCl = g_Rt_lo + (size_t)(U_DIM + u0) * U_DIM;

    // cp.async: each of 512 threads copies one 16B granule per 128x32 tile
    const int gr = tid >> 2;                   // row 0..127
    const int gc = tid & 3;                    // 16B col group
    const uint32_t gdst = (uint32_t)(gr * RS + gc * 16);
    const size_t   gsrc = (size_t)gr * U_DIM + gc * 8;

#define LOADC(k0, stg) do { \
        const uint32_t s = tiles + (stg) * STAGE; \
        CP16(s + ST_A_HI + gdst, (const char*)(pAh + gsrc + (k0))); \
        CP16(s + ST_A_LO + gdst, (const char*)(pAl + gsrc + (k0))); \
        CP16(s + ST_BF_HI + gdst, (const char*)(pFh + gsrc + (k0))); \
        CP16(s + ST_BF_LO + gdst, (const char*)(pFl + gsrc + (k0))); \
        CP16(s + ST_BC_HI + gdst, (const char*)(pCh + gsrc + (k0))); \
        CP16(s + ST_BC_LO + gdst, (const char*)(pCl + gsrc + (k0))); \
        CP_COMMIT(); \
    } while (0)

    // ldmatrix per-lane offsets
    const uint32_t aOff = (uint32_t)((mwarp * 32 + (lane & 15)) * RS + ((lane >> 4) << 4));
    // X4 B offset covering two adjacent n8 tiles
    const uint32_t bOff4 = (uint32_t)((nwarp * 32 + ((lane >> 4) << 3) + (lane & 7)) * RS +
                                      (((lane >> 3) & 1) << 4));

    float acc[2][2][4][4];   // [gate][mt][nt][e]
#pragma unroll
    for (int g = 0; g < 2; g++)
#pragma unroll
        for (int mt = 0; mt < 2; mt++)
#pragma unroll
            for (int nt = 0; nt < 4; nt++)
#pragma unroll
                for (int e = 0; e < 4; e++) acc[g][mt][nt][e] = 0.f;

    LOADC(0, 0);
    LOADC(KB, 1);

    int stg = 0;            // stage of chunk i
    int nstg = 2;           // stage for chunk i+2
    for (int i = 0; i < NCHUNK; i++) {
        // group i was committed 2 iterations ago; ensure it's complete
        if (i < NCHUNK - 1) { CP_WAIT1(); } else { CP_WAIT0(); }
        __syncthreads();    // stage i visible to all; all warps past chunk i-1 reads
        if (i + 2 < NCHUNK) {
            LOADC((i + 2) * KB, nstg);
            nstg = (nstg == NSTAGE - 1) ? 0 : nstg + 1;
        }

        const uint32_t base = tiles + stg * STAGE;
        stg = (stg == NSTAGE - 1) ? 0 : stg + 1;
        const uint32_t aHiB = base + ST_A_HI + aOff;
        const uint32_t aLoB = base + ST_A_LO + aOff;
        const uint32_t bHiB[2] = { base + ST_BF_HI + bOff4, base + ST_BC_HI + bOff4 };
        const uint32_t bLoB[2] = { base + ST_BF_LO + bOff4, base + ST_BC_LO + bOff4 };

#pragma unroll
        for (int kk = 0; kk < 2; kk++) {
            const uint32_t kb = kk * 32;  // 16 bf16 = 32 bytes
            uint32_t ah[2][4], al[2][4];
            LDSM_X4(ah[0], aHiB + kb);
            LDSM_X4(ah[1], aHiB + 16 * RS + kb);
            LDSM_X4(al[0], aLoB + kb);
            LDSM_X4(al[1], aLoB + 16 * RS + kb);
#pragma unroll
            for (int g = 0; g < 2; g++) {
                uint32_t bh[2][4], bl[2][4];   // [pair][4 regs: nt_even(2), nt_odd(2)]
#pragma unroll
                for (int p = 0; p < 2; p++) {
                    LDSM_X4(bh[p], bHiB[g] + p * 16 * RS + kb);
                    LDSM_X4(bl[p], bLoB[g] + p * 16 * RS + kb);
                }
#pragma unroll
                for (int mt = 0; mt < 2; mt++)
#pragma unroll
                    for (int nt = 0; nt < 4; nt++) {
                        const uint32_t* bhf = &bh[nt >> 1][(nt & 1) * 2];
                        const uint32_t* blf = &bl[nt >> 1][(nt & 1) * 2];
                        mma_bf16(acc[g][mt][nt], ah[mt], bhf);
                        mma_bf16(acc[g][mt][nt], al[mt], bhf);
                        mma_bf16(acc[g][mt][nt], ah[mt], blf);
                    }
            }
        }
    }
    __syncthreads();

    // -------- epilogue (in-register: this thread owns f and c for same elems) --------
    float ws[4] = {0.f, 0.f, 0.f, 0.f};
#pragma unroll
    for (int mt = 0; mt < 2; mt++) {
#pragma unroll
        for (int e2 = 0; e2 < 2; e2++) {
            const int rl = mwarp * 32 + mt * 16 + (lane >> 2) + e2 * 8;  // local row
            const int b = b0 + rl;
            const float x1v = g_x1[par][b];
            const __nv_bfloat16* __restrict__ ohi = g_h_hi[par] + (size_t)b * U_DIM + u0;
            const __nv_bfloat16* __restrict__ olo = g_h_lo[par] + (size_t)b * U_DIM + u0;
            __nv_bfloat16* __restrict__ hhi = g_h_hi[par ^ 1] + (size_t)b * U_DIM + u0;
            __nv_bfloat16* __restrict__ hlo = g_h_lo[par ^ 1] + (size_t)b * U_DIM + u0;
#pragma unroll
            for (int nt = 0; nt < 4; nt++) {
#pragma unroll
                for (int j = 0; j < 2; j++) {
                    const int e = e2 * 2 + j;
                    const int ul = nwarp * 32 + nt * 8 + (lane & 3) * 2 + j;  // local u (0..127)
                    const int ug = u0 + ul;
                    float xf = acc[0][mt][nt][e] + x1v * Kmat[ug] + bias[ug];
                    float xc = acc[1][mt][nt][e] + x1v * Kmat[U_DIM + ug] + bias[U_DIM + ug];
                    float fg = __fdividef(1.f, 1.f + __expf(-xf));
                    float th = 1.f - __fdividef(2.f, __expf(2.f * xc) + 1.f);
                    float ho = __bfloat162float(ohi[ul]) + __bfloat162float(olo[ul]);
                    float cv = fg * ho + (1.f - fg) * th;
                    __nv_bfloat16 hi = __float2bfloat16(cv);
                    hhi[ul] = hi;
                    hlo[ul] = __float2bfloat16(cv - __bfloat162float(hi));
                    ws[mt * 2 + e2] += cv * wout[ug];
                }
            }
        }
    }
    // reduce ws over the 4 lanes sharing each row, then across the 4 n-warps
#pragma unroll
    for (int w = 0; w < 4; w++) {
        float v = ws[w];
        v += __shfl_xor_sync(0xFFFFFFFFu, v, 1);
        v += __shfl_xor_sync(0xFFFFFFFFu, v, 2);
        if ((lane & 3) == 0) {
            const int rl = mwarp * 32 + (w >> 1) * 16 + (lane >> 2) + (w & 1) * 8;
            red[rl * 4 + nwarp] = v;
        }
    }
    __syncthreads();
    if (tid < 128)
        g_part[b0 + tid][blockIdx.x] =
            (red[tid * 4] + red[tid * 4 + 1]) + (red[tid * 4 + 2] + red[tid * 4 + 3]);

    // -------- last-CTA-per-b-row finisher: x1/x2/out update --------
    __threadfence();
    __syncthreads();
    if (tid == 0)
        sflag[0] = atomicAdd(&g_tick[t][blockIdx.y], 1);
    __syncthreads();
    if (sflag[0] == NTILE_U - 1) {
        __threadfence();   // acquire: make other CTAs' g_part writes visible
        if (tid < 128) {
            const int b = b0 + tid;
            float dot = 0.f;
#pragma unroll
            for (int n = 0; n < NTILE_U; n++) dot += g_part[b][n];
            float x1 = g_x1[par][b], x2 = g_x2[par][b];
            float x1n = x1 + x2;
            float x2n = x2 + inp[t * B_DIM + b] * dot;
            out[t * B_DIM + b] = x1n;
            g_x1[par ^ 1][b] = x1n;
            g_x2[par ^ 1][b] = x2n;
        }
    }
}

extern "C" void kernel_launch(void* const* d_in, const int* in_sizes, int n_in,
                              void* d_out, int out_size) {
    const float* inputs = (const float*)d_in[0];   // (T, B, 1)
    const float* x1_0   = (const float*)d_in[1];   // (B, 1)
    const float* x2_0   = (const float*)d_in[2];   // (B, 1)
    const float* c0     = (const float*)d_in[3];   // (B, U)
    const float* kmat   = (const float*)d_in[4];   // (1, 2U)
    const float* rker   = (const float*)d_in[5];   // (U, 2U)
    const float* bias   = (const float*)d_in[6];   // (2U)
    const float* wout   = (const float*)d_in[7];   // (U, 1)
    float* out = (float*)d_out;                    // (T, B, 1)
    (void)in_sizes; (void)n_in; (void)out_size;

    cudaFuncSetAttribute(step_gemm, cudaFuncAttributeMaxDynamicSharedMemorySize, SMEM_REQ);

    init_state<<<1024, 256>>>(x1_0, x2_0, c0);
    transpose_R<<<dim3(2 * U_DIM / 32, U_DIM / 32), dim3(32, 8)>>>(rker);

    dim3 grid(NTILE_U, NTILE_B);  // (8, 16)
    for (int t = 0; t < T_STEPS; t++)
        step_gemm<<<grid, 512, SMEM_REQ>>>(kmat, bias, wout, inputs, out, t);
}